// round 1
// baseline (speedup 1.0000x reference)
#include <cuda_runtime.h>
#include <cuda_bf16.h>
#include <math.h>

#define NN   50000
#define EE   800000
#define ETOT (EE + NN)
#define FIN  256
#define HC   128      // HEADS*C1 = 8*16
#define NC   40
#define NSLOPE 0.2f

// ---------------- scratch (static device globals; no allocation allowed) ----
__device__ int   g_is64;
__device__ int   g_src[ETOT];
__device__ int   g_dst[ETOT];
__device__ int   g_deg[NN];
__device__ int   g_off[NN + 1];
__device__ int   g_cur[NN];
__device__ int   g_csr[ETOT];          // source node per incoming edge, grouped by dst
__device__ float g_h1 [NN * HC];       // x @ W1
__device__ float g_as1[NN * 8];
__device__ float g_ad1[NN * 8];
__device__ float g_out1[NN * HC];      // elu(gat1 + b1)
__device__ float g_h2 [NN * NC];       // out1 @ W2
__device__ float g_as2[NN];
__device__ float g_ad2[NN];

// ---------------- edge preprocessing ---------------------------------------
__global__ void detect_kernel(const void* ei) {
    // int64 little-endian: high 32-bit words are 0 (values in [0,50000))
    const unsigned int* u = (const unsigned int*)ei;
    int is64 = 1;
    for (int i = 0; i < 8; i++)
        if (u[2 * i + 1] != 0u) is64 = 0;
    g_is64 = is64;
}

__global__ void build_edges_kernel(const void* ei) {
    int e = blockIdx.x * blockDim.x + threadIdx.x;
    if (e >= ETOT) return;
    int s, d;
    if (e < EE) {
        if (g_is64) {
            const long long* p = (const long long*)ei;
            s = (int)p[e]; d = (int)p[EE + e];
        } else {
            const int* p = (const int*)ei;
            s = p[e]; d = p[EE + e];
        }
    } else {
        s = d = e - EE;    // self loops
    }
    g_src[e] = s;
    g_dst[e] = d;
}

__global__ void zero_deg_kernel() {
    int i = blockIdx.x * blockDim.x + threadIdx.x;
    if (i < NN) g_deg[i] = 0;
}

__global__ void hist_kernel() {
    int e = blockIdx.x * blockDim.x + threadIdx.x;
    if (e >= ETOT) return;
    atomicAdd(&g_deg[g_dst[e]], 1);
}

__global__ void scan_kernel() {
    __shared__ int sdata[1024];
    int tid = threadIdx.x;
    int carry = 0;
    for (int base = 0; base < NN; base += 1024) {
        int i = base + tid;
        int v = (i < NN) ? g_deg[i] : 0;
        sdata[tid] = v;
        __syncthreads();
        for (int ofs = 1; ofs < 1024; ofs <<= 1) {
            int t = 0;
            if (tid >= ofs) t = sdata[tid - ofs];
            __syncthreads();
            sdata[tid] += t;
            __syncthreads();
        }
        int incl  = sdata[tid];
        int total = sdata[1023];
        int excl  = carry + incl - v;
        if (i < NN) { g_off[i] = excl; g_cur[i] = excl; }
        carry += total;
        __syncthreads();
    }
    if (tid == 0) g_off[NN] = carry;
}

__global__ void scatter_kernel() {
    int e = blockIdx.x * blockDim.x + threadIdx.x;
    if (e >= ETOT) return;
    int d = g_dst[e];
    int slot = atomicAdd(&g_cur[d], 1);
    g_csr[slot] = g_src[e];
}

// ---------------- GEMM1: h1 = x[NN,256] @ W1[256,128] -----------------------
// BM=64, BN=128(full), BK=16, 256 threads, 4x8 per thread
__global__ __launch_bounds__(256) void gemm1_kernel(const float* __restrict__ A,
                                                    const float* __restrict__ B) {
    __shared__ float As[16][68];    // padded: conflict-free stores, 16B-aligned rows
    __shared__ float Bs[16][128];
    int row0 = blockIdx.x * 64;
    int t  = threadIdx.x;
    int tx = t & 15;     // col group (x8)
    int ty = t >> 4;     // row group (x4)

    float acc[4][8];
#pragma unroll
    for (int i = 0; i < 4; i++)
#pragma unroll
        for (int j = 0; j < 8; j++) acc[i][j] = 0.f;

    for (int k0 = 0; k0 < FIN; k0 += 16) {
        {   // A tile: 64 rows x 16 k -> one float4 per thread
            int m  = t >> 2;
            int kq = (t & 3) * 4;
            int gr = row0 + m;
            float4 v = make_float4(0.f, 0.f, 0.f, 0.f);
            if (gr < NN) v = *(const float4*)&A[gr * FIN + k0 + kq];
            As[kq + 0][m] = v.x; As[kq + 1][m] = v.y;
            As[kq + 2][m] = v.z; As[kq + 3][m] = v.w;
        }
        {   // B tile: 16 k x 128 n -> two float4 per thread
            int kk = t >> 5;
            int n  = (t & 31) * 4;
            *(float4*)&Bs[kk][n]     = *(const float4*)&B[(k0 + kk) * HC + n];
            *(float4*)&Bs[kk + 8][n] = *(const float4*)&B[(k0 + kk + 8) * HC + n];
        }
        __syncthreads();
#pragma unroll
        for (int k = 0; k < 16; k++) {
            float4 ra  = *(const float4*)&As[k][ty * 4];
            float4 rb0 = *(const float4*)&Bs[k][tx * 8];
            float4 rb1 = *(const float4*)&Bs[k][tx * 8 + 4];
            float ar[4] = {ra.x, ra.y, ra.z, ra.w};
            float br[8] = {rb0.x, rb0.y, rb0.z, rb0.w, rb1.x, rb1.y, rb1.z, rb1.w};
#pragma unroll
            for (int i = 0; i < 4; i++)
#pragma unroll
                for (int j = 0; j < 8; j++) acc[i][j] += ar[i] * br[j];
        }
        __syncthreads();
    }
#pragma unroll
    for (int i = 0; i < 4; i++) {
        int gr = row0 + ty * 4 + i;
        if (gr < NN) {
            float4 v0 = make_float4(acc[i][0], acc[i][1], acc[i][2], acc[i][3]);
            float4 v1 = make_float4(acc[i][4], acc[i][5], acc[i][6], acc[i][7]);
            *(float4*)&g_h1[gr * HC + tx * 8]     = v0;
            *(float4*)&g_h1[gr * HC + tx * 8 + 4] = v1;
        }
    }
}

// ---------------- attention logits layer 1 ----------------------------------
__global__ void att1_kernel(const float* __restrict__ asv, const float* __restrict__ adv) {
    int idx = blockIdx.x * blockDim.x + threadIdx.x;
    if (idx >= NN * 8) return;
    int n = idx >> 3, h = idx & 7;
    const float* row = &g_h1[n * HC + h * 16];
    float s = 0.f, d = 0.f;
#pragma unroll
    for (int c = 0; c < 16; c++) {
        float v = row[c];
        s += v * asv[h * 16 + c];
        d += v * adv[h * 16 + c];
    }
    g_as1[idx] = s;
    g_ad1[idx] = d;
}

// ---------------- layer 1 aggregation: warp per destination node -------------
__global__ __launch_bounds__(256) void agg1_kernel(const float* __restrict__ b1) {
    int gw = (blockIdx.x * blockDim.x + threadIdx.x) >> 5;
    int lane = threadIdx.x & 31;
    if (gw >= NN) return;
    int n = gw;
    int beg = g_off[n], end = g_off[n + 1];

    int h8 = lane & 7;          // head for max phase (and exp phase on lanes<8)
    int eg = lane >> 3;         // 4 edge groups
    float adst = g_ad1[n * 8 + h8];

    // pass 1: per-head max, edges strided across 4 lane groups
    float mymax = -1e30f;
    for (int i = beg + eg; i < end; i += 4) {
        int s = g_csr[i];
        float ev = g_as1[s * 8 + h8] + adst;
        ev = ev > 0.f ? ev : NSLOPE * ev;
        mymax = fmaxf(mymax, ev);
    }
    mymax = fmaxf(mymax, __shfl_xor_sync(0xffffffffu, mymax, 8));
    mymax = fmaxf(mymax, __shfl_xor_sync(0xffffffffu, mymax, 16));
    float m = mymax;            // lanes<8 hold m for head=lane

    // pass 2: whole warp per edge; lanes<8 compute p per head, all lanes accumulate
    float acc0 = 0.f, acc1 = 0.f, acc2 = 0.f, acc3 = 0.f;
    float denom = 0.f;
    int head = lane >> 2;       // channel block lane*4 -> head = lane/4
    const float4* h1v = (const float4*)g_h1;
    for (int i = beg; i < end; i++) {
        int s = g_csr[i];
        float p = 0.f;
        if (lane < 8) {
            float ev = g_as1[s * 8 + lane] + adst;
            ev = ev > 0.f ? ev : NSLOPE * ev;
            p = __expf(ev - m);
            denom += p;
        }
        float ph = __shfl_sync(0xffffffffu, p, head);
        float4 hv = h1v[s * 32 + lane];
        acc0 += ph * hv.x; acc1 += ph * hv.y;
        acc2 += ph * hv.z; acc3 += ph * hv.w;
    }
    float dh = __shfl_sync(0xffffffffu, denom, head);
    float inv = 1.f / (dh + 1e-16f);
    int ch = lane * 4;
    float v[4] = {acc0 * inv + b1[ch], acc1 * inv + b1[ch + 1],
                  acc2 * inv + b1[ch + 2], acc3 * inv + b1[ch + 3]};
#pragma unroll
    for (int j = 0; j < 4; j++)
        v[j] = v[j] > 0.f ? v[j] : expm1f(v[j]);   // ELU
    float4 ov = make_float4(v[0], v[1], v[2], v[3]);
    ((float4*)g_out1)[n * 32 + lane] = ov;
}

// ---------------- GEMM2: h2 = out1[NN,128] @ W2[128,40] ----------------------
__global__ __launch_bounds__(320) void gemm2_kernel(const float* __restrict__ W) {
    __shared__ float s_w[HC * NC];       // 20 KB
    __shared__ float s_x[32][HC];        // 16 KB
    int c = threadIdx.x;   // 0..39
    int r = threadIdx.y;   // 0..7
    int t = threadIdx.y * 40 + threadIdx.x;
    int row0 = blockIdx.x * 32;

    for (int i = t; i < HC * NC; i += 320) s_w[i] = W[i];
    for (int i = t; i < 32 * HC; i += 320) {
        int rr = i >> 7, kk = i & 127;
        int gr = row0 + rr;
        s_x[rr][kk] = (gr < NN) ? g_out1[gr * HC + kk] : 0.f;
    }
    __syncthreads();

    float acc[4] = {0.f, 0.f, 0.f, 0.f};
    for (int k = 0; k < HC; k++) {
        float w = s_w[k * NC + c];
        acc[0] += w * s_x[r][k];
        acc[1] += w * s_x[r + 8][k];
        acc[2] += w * s_x[r + 16][k];
        acc[3] += w * s_x[r + 24][k];
    }
#pragma unroll
    for (int i = 0; i < 4; i++) {
        int gr = row0 + r + 8 * i;
        if (gr < NN) g_h2[gr * NC + c] = acc[i];
    }
}

// ---------------- attention logits layer 2 (warp per node) -------------------
__global__ __launch_bounds__(256) void att2_kernel(const float* __restrict__ asv,
                                                   const float* __restrict__ adv) {
    int gw = (blockIdx.x * blockDim.x + threadIdx.x) >> 5;
    int lane = threadIdx.x & 31;
    if (gw >= NN) return;
    int n = gw;
    float v0 = g_h2[n * NC + lane];
    float s = v0 * asv[lane];
    float d = v0 * adv[lane];
    if (lane < 8) {
        float v1 = g_h2[n * NC + 32 + lane];
        s += v1 * asv[32 + lane];
        d += v1 * adv[32 + lane];
    }
#pragma unroll
    for (int o = 16; o > 0; o >>= 1) {
        s += __shfl_xor_sync(0xffffffffu, s, o);
        d += __shfl_xor_sync(0xffffffffu, d, o);
    }
    if (lane == 0) { g_as2[n] = s; g_ad2[n] = d; }
}

// ---------------- layer 2 aggregation + log_softmax + output -----------------
__global__ __launch_bounds__(256) void agg2_kernel(const float* __restrict__ b2,
                                                   float* __restrict__ out,
                                                   int write_both) {
    int gw = (blockIdx.x * blockDim.x + threadIdx.x) >> 5;
    int lane = threadIdx.x & 31;
    if (gw >= NN) return;
    int n = gw;
    int beg = g_off[n], end = g_off[n + 1];
    float adst = g_ad2[n];

    float mymax = -1e30f;
    for (int i = beg + lane; i < end; i += 32) {
        int s = g_csr[i];
        float ev = g_as2[s] + adst;
        ev = ev > 0.f ? ev : NSLOPE * ev;
        mymax = fmaxf(mymax, ev);
    }
#pragma unroll
    for (int o = 16; o > 0; o >>= 1)
        mymax = fmaxf(mymax, __shfl_xor_sync(0xffffffffu, mymax, o));
    float m = mymax;

    float acc0 = 0.f, acc1 = 0.f, denom = 0.f;
    for (int i = beg; i < end; i++) {
        int s = g_csr[i];
        float ev = g_as2[s] + adst;
        ev = ev > 0.f ? ev : NSLOPE * ev;
        float p = __expf(ev - m);
        denom += p;
        acc0 += p * g_h2[s * NC + lane];
        if (lane < 8) acc1 += p * g_h2[s * NC + 32 + lane];
    }
    float inv = 1.f / (denom + 1e-16f);
    float v0 = acc0 * inv + b2[lane];
    float v1 = (lane < 8) ? acc1 * inv + b2[32 + lane] : -1e30f;

    // log_softmax over 40 classes
    float rmax = fmaxf(v0, v1);
#pragma unroll
    for (int o = 16; o > 0; o >>= 1)
        rmax = fmaxf(rmax, __shfl_xor_sync(0xffffffffu, rmax, o));
    float se = expf(v0 - rmax) + ((lane < 8) ? expf(v1 - rmax) : 0.f);
#pragma unroll
    for (int o = 16; o > 0; o >>= 1)
        se += __shfl_xor_sync(0xffffffffu, se, o);
    float lse = rmax + logf(se);

    out[n * NC + lane] = v0;
    if (lane < 8) out[n * NC + 32 + lane] = v1;
    if (write_both) {
        float* o2 = out + (size_t)NN * NC;
        o2[n * NC + lane] = v0 - lse;
        if (lane < 8) o2[n * NC + 32 + lane] = v1 - lse;
    }
}

// ---------------- launch -----------------------------------------------------
extern "C" void kernel_launch(void* const* d_in, const int* in_sizes, int n_in,
                              void* d_out, int out_size) {
    const float* x   = (const float*)d_in[0];
    const void*  ei  = d_in[1];
    const float* W1  = (const float*)d_in[3];
    const float* as1 = (const float*)d_in[4];
    const float* ad1 = (const float*)d_in[5];
    const float* b1  = (const float*)d_in[6];
    const float* W2  = (const float*)d_in[7];
    const float* as2 = (const float*)d_in[8];
    const float* ad2 = (const float*)d_in[9];
    const float* b2  = (const float*)d_in[10];
    float* out = (float*)d_out;

    (void)in_sizes; (void)n_in;

    detect_kernel<<<1, 1>>>(ei);
    build_edges_kernel<<<(ETOT + 255) / 256, 256>>>(ei);
    zero_deg_kernel<<<(NN + 255) / 256, 256>>>();
    hist_kernel<<<(ETOT + 255) / 256, 256>>>();
    scan_kernel<<<1, 1024>>>();
    scatter_kernel<<<(ETOT + 255) / 256, 256>>>();

    gemm1_kernel<<<(NN + 63) / 64, 256>>>(x, W1);
    att1_kernel<<<(NN * 8 + 255) / 256, 256>>>(as1, ad1);
    agg1_kernel<<<(NN * 32 + 255) / 256, 256>>>(b1);

    gemm2_kernel<<<(NN + 31) / 32, dim3(40, 8)>>>(W2);
    att2_kernel<<<(NN * 32 + 255) / 256, 256>>>(as2, ad2);

    int write_both = (out_size >= 2 * NN * NC) ? 1 : 0;
    agg2_kernel<<<(NN * 32 + 255) / 256, 256>>>(b2, out, write_both);
}

// round 2
// speedup vs baseline: 1.3800x; 1.3800x over previous
#include <cuda_runtime.h>
#include <cuda_bf16.h>
#include <math.h>

#define NN   50000
#define EE   800000
#define ETOT (EE + NN)
#define FIN  256
#define HC   128      // HEADS*C1 = 8*16
#define NC   40
#define NSLOPE 0.2f
#define NB_SCAN ((NN + 1023) / 1024)   // 49

// ---------------- scratch -----------------------------------------------
__device__ int   g_is64;
__device__ int   g_src[ETOT];
__device__ int   g_dst[ETOT];
__device__ int   g_deg[NN];
__device__ int   g_off[NN + 1];
__device__ int   g_cur[NN];
__device__ int   g_csr[ETOT];
__device__ int   g_bsum[64];
__device__ int   g_boff[64];
__device__ float g_h1 [NN * HC];
__device__ float g_as1[NN * 8];
__device__ float g_ad1[NN * 8];
__device__ float g_out1[NN * HC];
__device__ float g_h2 [NN * NC];
__device__ float g_as2[NN];
__device__ float g_ad2[NN];

// packed fp32x2 FMA (sm_100+): two independent fp32 FMAs per instruction
union F2 { unsigned long long u; float2 f; };
__device__ __forceinline__ void fma2(unsigned long long& d,
                                     unsigned long long a,
                                     unsigned long long b) {
    asm("fma.rn.f32x2 %0, %1, %2, %0;" : "+l"(d) : "l"(a), "l"(b));
}

// ---------------- preprocessing -----------------------------------------
__global__ void init_kernel(const void* ei) {
    int i = blockIdx.x * blockDim.x + threadIdx.x;
    if (i < NN) g_deg[i] = 0;
    if (blockIdx.x == 0 && threadIdx.x == 0) {
        const unsigned int* u = (const unsigned int*)ei;
        int is64 = 1;
        for (int k = 0; k < 8; k++)
            if (u[2 * k + 1] != 0u) is64 = 0;
        g_is64 = is64;
    }
}

__global__ void build_hist_kernel(const void* ei) {
    int e = blockIdx.x * blockDim.x + threadIdx.x;
    if (e >= ETOT) return;
    int s, d;
    if (e < EE) {
        if (g_is64) {
            const long long* p = (const long long*)ei;
            s = (int)p[e]; d = (int)p[EE + e];
        } else {
            const int* p = (const int*)ei;
            s = p[e]; d = p[EE + e];
        }
    } else {
        s = d = e - EE;
    }
    g_src[e] = s;
    g_dst[e] = d;
    atomicAdd(&g_deg[d], 1);
}

__global__ void scan1_kernel() {
    __shared__ int sd[1024];
    int tid = threadIdx.x;
    int i = blockIdx.x * 1024 + tid;
    int v = (i < NN) ? g_deg[i] : 0;
    sd[tid] = v;
    __syncthreads();
    for (int ofs = 1; ofs < 1024; ofs <<= 1) {
        int t = (tid >= ofs) ? sd[tid - ofs] : 0;
        __syncthreads();
        sd[tid] += t;
        __syncthreads();
    }
    if (i < NN) g_off[i] = sd[tid];            // inclusive within block
    if (tid == 1023) g_bsum[blockIdx.x] = sd[tid];
}

__global__ void scan2_kernel() {
    __shared__ int sd[64];
    int tid = threadIdx.x;
    int v = (tid < NB_SCAN) ? g_bsum[tid] : 0;
    sd[tid] = v;
    __syncthreads();
    for (int ofs = 1; ofs < 64; ofs <<= 1) {
        int t = (tid >= ofs) ? sd[tid - ofs] : 0;
        __syncthreads();
        sd[tid] += t;
        __syncthreads();
    }
    g_boff[tid] = sd[tid] - v;                 // exclusive
}

__global__ void scan3_kernel() {
    int i = blockIdx.x * blockDim.x + threadIdx.x;
    if (i < NN) {
        int excl = g_off[i] - g_deg[i] + g_boff[i >> 10];
        g_off[i] = excl;
        g_cur[i] = excl;
    }
    if (i == 0) g_off[NN] = ETOT;
}

__global__ void scatter_kernel() {
    int e = blockIdx.x * blockDim.x + threadIdx.x;
    if (e >= ETOT) return;
    int slot = atomicAdd(&g_cur[g_dst[e]], 1);
    g_csr[slot] = g_src[e];
}

// ---------------- GEMM1 + fused att1 ------------------------------------
// h1 = x[NN,256] @ W1[256,128]; per-thread 8x8 with f32x2 pairs along N.
// BM=128, BN=128, BK=16, 256 threads, double-buffered smem.
__global__ __launch_bounds__(256) void gemm1_kernel(const float* __restrict__ A,
                                                    const float* __restrict__ B,
                                                    const float* __restrict__ asv,
                                                    const float* __restrict__ adv) {
    __shared__ float As[2][16][132];
    __shared__ float Bs[2][16][128];
    int t = threadIdx.x;
    int row0 = blockIdx.x * 128;
    int tx = t & 15, ty = t >> 4;

    int am = t >> 1;            // A tile row 0..127
    int ak = (t & 1) * 8;       // A tile k offset 0/8
    int bk = t >> 4;            // B tile k 0..15
    int bn = (t & 15) * 8;      // B tile n

    F2 acc[8][4];
#pragma unroll
    for (int i = 0; i < 8; i++)
#pragma unroll
        for (int j = 0; j < 4; j++) acc[i][j].u = 0ull;

    float4 a0, a1, b0, b1;
    {   // tile 0 loads
        int gr = row0 + am;
        if (gr < NN) {
            a0 = *(const float4*)&A[gr * FIN + ak];
            a1 = *(const float4*)&A[gr * FIN + ak + 4];
        } else { a0 = a1 = make_float4(0.f, 0.f, 0.f, 0.f); }
        b0 = *(const float4*)&B[bk * HC + bn];
        b1 = *(const float4*)&B[bk * HC + bn + 4];
    }
    As[0][ak + 0][am] = a0.x; As[0][ak + 1][am] = a0.y;
    As[0][ak + 2][am] = a0.z; As[0][ak + 3][am] = a0.w;
    As[0][ak + 4][am] = a1.x; As[0][ak + 5][am] = a1.y;
    As[0][ak + 6][am] = a1.z; As[0][ak + 7][am] = a1.w;
    *(float4*)&Bs[0][bk][bn]     = b0;
    *(float4*)&Bs[0][bk][bn + 4] = b1;
    __syncthreads();

    for (int it = 0; it < 16; it++) {
        int cur = it & 1;
        if (it < 15) {
            int k0 = (it + 1) * 16;
            int gr = row0 + am;
            if (gr < NN) {
                a0 = *(const float4*)&A[gr * FIN + k0 + ak];
                a1 = *(const float4*)&A[gr * FIN + k0 + ak + 4];
            } else { a0 = a1 = make_float4(0.f, 0.f, 0.f, 0.f); }
            b0 = *(const float4*)&B[(k0 + bk) * HC + bn];
            b1 = *(const float4*)&B[(k0 + bk) * HC + bn + 4];
        }
#pragma unroll
        for (int k = 0; k < 16; k++) {
            float4 ra0 = *(const float4*)&As[cur][k][ty * 8];
            float4 ra1 = *(const float4*)&As[cur][k][ty * 8 + 4];
            const float2* pb = (const float2*)&Bs[cur][k][tx * 8];
            F2 bb[4];
#pragma unroll
            for (int j = 0; j < 4; j++) bb[j].f = pb[j];
            float av[8] = {ra0.x, ra0.y, ra0.z, ra0.w, ra1.x, ra1.y, ra1.z, ra1.w};
#pragma unroll
            for (int i = 0; i < 8; i++) {
                F2 ad; ad.f.x = av[i]; ad.f.y = av[i];
#pragma unroll
                for (int j = 0; j < 4; j++) fma2(acc[i][j].u, ad.u, bb[j].u);
            }
        }
        if (it < 15) {
            int nb = cur ^ 1;
            As[nb][ak + 0][am] = a0.x; As[nb][ak + 1][am] = a0.y;
            As[nb][ak + 2][am] = a0.z; As[nb][ak + 3][am] = a0.w;
            As[nb][ak + 4][am] = a1.x; As[nb][ak + 5][am] = a1.y;
            As[nb][ak + 6][am] = a1.z; As[nb][ak + 7][am] = a1.w;
            *(float4*)&Bs[nb][bk][bn]     = b0;
            *(float4*)&Bs[nb][bk][bn + 4] = b1;
            __syncthreads();
        }
    }

    // epilogue: store h1 + fused attention logits
    int head = tx >> 1;
    int abase = head * 16 + (tx & 1) * 8;
    float asr[8], adr[8];
#pragma unroll
    for (int j = 0; j < 8; j++) { asr[j] = asv[abase + j]; adr[j] = adv[abase + j]; }

#pragma unroll
    for (int i = 0; i < 8; i++) {
        int gr = row0 + ty * 8 + i;
        float h[8];
#pragma unroll
        for (int j = 0; j < 4; j++) { h[2 * j] = acc[i][j].f.x; h[2 * j + 1] = acc[i][j].f.y; }
        if (gr < NN) {
            *(float4*)&g_h1[gr * HC + tx * 8]     = make_float4(h[0], h[1], h[2], h[3]);
            *(float4*)&g_h1[gr * HC + tx * 8 + 4] = make_float4(h[4], h[5], h[6], h[7]);
        }
        float s = 0.f, d = 0.f;
#pragma unroll
        for (int j = 0; j < 8; j++) { s += h[j] * asr[j]; d += h[j] * adr[j]; }
        s += __shfl_xor_sync(0xffffffffu, s, 1);
        d += __shfl_xor_sync(0xffffffffu, d, 1);
        if (((t & 1) == 0) && gr < NN) {
            g_as1[gr * 8 + head] = s;
            g_ad1[gr * 8 + head] = d;
        }
    }
}

// ---------------- layer 1 aggregation -----------------------------------
__global__ __launch_bounds__(256) void agg1_kernel(const float* __restrict__ b1) {
    int gw = (blockIdx.x * blockDim.x + threadIdx.x) >> 5;
    int lane = threadIdx.x & 31;
    if (gw >= NN) return;
    int n = gw;
    int beg = g_off[n], end = g_off[n + 1];

    int h8 = lane & 7;
    int eg = lane >> 3;
    float adst = g_ad1[n * 8 + h8];

    float mymax = -1e30f;
    for (int i = beg + eg; i < end; i += 4) {
        int s = g_csr[i];
        float ev = g_as1[s * 8 + h8] + adst;
        ev = ev > 0.f ? ev : NSLOPE * ev;
        mymax = fmaxf(mymax, ev);
    }
    mymax = fmaxf(mymax, __shfl_xor_sync(0xffffffffu, mymax, 8));
    mymax = fmaxf(mymax, __shfl_xor_sync(0xffffffffu, mymax, 16));
    float m = mymax;

    float acc0 = 0.f, acc1 = 0.f, acc2 = 0.f, acc3 = 0.f;
    float denom = 0.f;
    int head = lane >> 2;
    const float4* h1v = (const float4*)g_h1;

    int i = beg;
    for (; i + 2 <= end; i += 2) {
        int s0 = g_csr[i], s1 = g_csr[i + 1];
        float4 hv0 = h1v[s0 * 32 + lane];
        float4 hv1 = h1v[s1 * 32 + lane];
        float p0 = 0.f, p1 = 0.f;
        if (lane < 8) {
            float e0 = g_as1[s0 * 8 + lane] + adst;
            e0 = e0 > 0.f ? e0 : NSLOPE * e0;
            p0 = __expf(e0 - m);
            float e1 = g_as1[s1 * 8 + lane] + adst;
            e1 = e1 > 0.f ? e1 : NSLOPE * e1;
            p1 = __expf(e1 - m);
            denom += p0 + p1;
        }
        float ph0 = __shfl_sync(0xffffffffu, p0, head);
        float ph1 = __shfl_sync(0xffffffffu, p1, head);
        acc0 += ph0 * hv0.x + ph1 * hv1.x;
        acc1 += ph0 * hv0.y + ph1 * hv1.y;
        acc2 += ph0 * hv0.z + ph1 * hv1.z;
        acc3 += ph0 * hv0.w + ph1 * hv1.w;
    }
    for (; i < end; i++) {
        int s = g_csr[i];
        float4 hv = h1v[s * 32 + lane];
        float p = 0.f;
        if (lane < 8) {
            float ev = g_as1[s * 8 + lane] + adst;
            ev = ev > 0.f ? ev : NSLOPE * ev;
            p = __expf(ev - m);
            denom += p;
        }
        float ph = __shfl_sync(0xffffffffu, p, head);
        acc0 += ph * hv.x; acc1 += ph * hv.y;
        acc2 += ph * hv.z; acc3 += ph * hv.w;
    }
    float dh = __shfl_sync(0xffffffffu, denom, head);
    float inv = 1.f / (dh + 1e-16f);
    int ch = lane * 4;
    float v[4] = {acc0 * inv + b1[ch], acc1 * inv + b1[ch + 1],
                  acc2 * inv + b1[ch + 2], acc3 * inv + b1[ch + 3]};
#pragma unroll
    for (int j = 0; j < 4; j++)
        v[j] = v[j] > 0.f ? v[j] : expm1f(v[j]);
    ((float4*)g_out1)[n * 32 + lane] = make_float4(v[0], v[1], v[2], v[3]);
}

// ---------------- GEMM2: h2 = out1[NN,128] @ W2[128,40] ------------------
__global__ __launch_bounds__(320) void gemm2_kernel(const float* __restrict__ W) {
    __shared__ float s_w[HC * NC];       // 20 KB
    __shared__ float s_x[64][HC];        // 32 KB
    int c = threadIdx.x;   // 0..39
    int r = threadIdx.y;   // 0..7
    int t = threadIdx.y * 40 + threadIdx.x;
    int row0 = blockIdx.x * 64;

    for (int i = t; i < HC * NC; i += 320) s_w[i] = W[i];
    for (int i = t; i < 64 * (HC / 4); i += 320) {
        int rr = i >> 5, kq = (i & 31) * 4;
        int gr = row0 + rr;
        float4 v = make_float4(0.f, 0.f, 0.f, 0.f);
        if (gr < NN) v = *(const float4*)&g_out1[gr * HC + kq];
        *(float4*)&s_x[rr][kq] = v;
    }
    __syncthreads();

    float acc[8] = {0.f, 0.f, 0.f, 0.f, 0.f, 0.f, 0.f, 0.f};
    for (int k4 = 0; k4 < HC; k4 += 4) {
        float w0 = s_w[(k4 + 0) * NC + c];
        float w1 = s_w[(k4 + 1) * NC + c];
        float w2 = s_w[(k4 + 2) * NC + c];
        float w3 = s_w[(k4 + 3) * NC + c];
#pragma unroll
        for (int i = 0; i < 8; i++) {
            float4 xv = *(const float4*)&s_x[r + 8 * i][k4];
            acc[i] += w0 * xv.x + w1 * xv.y + w2 * xv.z + w3 * xv.w;
        }
    }
#pragma unroll
    for (int i = 0; i < 8; i++) {
        int gr = row0 + r + 8 * i;
        if (gr < NN) g_h2[gr * NC + c] = acc[i];
    }
}

// ---------------- attention logits layer 2 --------------------------------
__global__ __launch_bounds__(256) void att2_kernel(const float* __restrict__ asv,
                                                   const float* __restrict__ adv) {
    int gw = (blockIdx.x * blockDim.x + threadIdx.x) >> 5;
    int lane = threadIdx.x & 31;
    if (gw >= NN) return;
    int n = gw;
    float v0 = g_h2[n * NC + lane];
    float s = v0 * asv[lane];
    float d = v0 * adv[lane];
    if (lane < 8) {
        float v1 = g_h2[n * NC + 32 + lane];
        s += v1 * asv[32 + lane];
        d += v1 * adv[32 + lane];
    }
#pragma unroll
    for (int o = 16; o > 0; o >>= 1) {
        s += __shfl_xor_sync(0xffffffffu, s, o);
        d += __shfl_xor_sync(0xffffffffu, d, o);
    }
    if (lane == 0) { g_as2[n] = s; g_ad2[n] = d; }
}

// ---------------- layer 2 aggregation + log_softmax ----------------------
__global__ __launch_bounds__(256) void agg2_kernel(const float* __restrict__ b2,
                                                   float* __restrict__ out,
                                                   int write_both) {
    int gw = (blockIdx.x * blockDim.x + threadIdx.x) >> 5;
    int lane = threadIdx.x & 31;
    if (gw >= NN) return;
    int n = gw;
    int beg = g_off[n], end = g_off[n + 1];
    float adst = g_ad2[n];

    float mymax = -1e30f;
    for (int i = beg + lane; i < end; i += 32) {
        int s = g_csr[i];
        float ev = g_as2[s] + adst;
        ev = ev > 0.f ? ev : NSLOPE * ev;
        mymax = fmaxf(mymax, ev);
    }
#pragma unroll
    for (int o = 16; o > 0; o >>= 1)
        mymax = fmaxf(mymax, __shfl_xor_sync(0xffffffffu, mymax, o));
    float m = mymax;

    float acc0 = 0.f, acc1 = 0.f, denom = 0.f;
    int i = beg;
    for (; i + 2 <= end; i += 2) {
        int s0 = g_csr[i], s1 = g_csr[i + 1];
        float x00 = g_h2[s0 * NC + lane];
        float x10 = g_h2[s1 * NC + lane];
        float x01 = (lane < 8) ? g_h2[s0 * NC + 32 + lane] : 0.f;
        float x11 = (lane < 8) ? g_h2[s1 * NC + 32 + lane] : 0.f;
        float e0 = g_as2[s0] + adst; e0 = e0 > 0.f ? e0 : NSLOPE * e0;
        float e1 = g_as2[s1] + adst; e1 = e1 > 0.f ? e1 : NSLOPE * e1;
        float p0 = __expf(e0 - m), p1 = __expf(e1 - m);
        denom += p0 + p1;
        acc0 += p0 * x00 + p1 * x10;
        acc1 += p0 * x01 + p1 * x11;
    }
    for (; i < end; i++) {
        int s = g_csr[i];
        float x0 = g_h2[s * NC + lane];
        float x1 = (lane < 8) ? g_h2[s * NC + 32 + lane] : 0.f;
        float ev = g_as2[s] + adst;
        ev = ev > 0.f ? ev : NSLOPE * ev;
        float p = __expf(ev - m);
        denom += p;
        acc0 += p * x0;
        acc1 += p * x1;
    }
    float inv = 1.f / (denom + 1e-16f);
    float v0 = acc0 * inv + b2[lane];
    float v1 = (lane < 8) ? acc1 * inv + b2[32 + lane] : -1e30f;

    float rmax = fmaxf(v0, v1);
#pragma unroll
    for (int o = 16; o > 0; o >>= 1)
        rmax = fmaxf(rmax, __shfl_xor_sync(0xffffffffu, rmax, o));
    float se = expf(v0 - rmax) + ((lane < 8) ? expf(v1 - rmax) : 0.f);
#pragma unroll
    for (int o = 16; o > 0; o >>= 1)
        se += __shfl_xor_sync(0xffffffffu, se, o);
    float lse = rmax + logf(se);

    out[n * NC + lane] = v0;
    if (lane < 8) out[n * NC + 32 + lane] = v1;
    if (write_both) {
        float* o2 = out + (size_t)NN * NC;
        o2[n * NC + lane] = v0 - lse;
        if (lane < 8) o2[n * NC + 32 + lane] = v1 - lse;
    }
}

// ---------------- launch --------------------------------------------------
extern "C" void kernel_launch(void* const* d_in, const int* in_sizes, int n_in,
                              void* d_out, int out_size) {
    const float* x   = (const float*)d_in[0];
    const void*  ei  = d_in[1];
    const float* W1  = (const float*)d_in[3];
    const float* as1 = (const float*)d_in[4];
    const float* ad1 = (const float*)d_in[5];
    const float* b1  = (const float*)d_in[6];
    const float* W2  = (const float*)d_in[7];
    const float* as2 = (const float*)d_in[8];
    const float* ad2 = (const float*)d_in[9];
    const float* b2  = (const float*)d_in[10];
    float* out = (float*)d_out;
    (void)in_sizes; (void)n_in;

    init_kernel<<<(NN + 255) / 256, 256>>>(ei);
    build_hist_kernel<<<(ETOT + 255) / 256, 256>>>(ei);
    scan1_kernel<<<NB_SCAN, 1024>>>();
    scan2_kernel<<<1, 64>>>();
    scan3_kernel<<<(NN + 255) / 256, 256>>>();
    scatter_kernel<<<(ETOT + 255) / 256, 256>>>();

    gemm1_kernel<<<(NN + 127) / 128, 256>>>(x, W1, as1, ad1);
    agg1_kernel<<<(NN * 32 + 255) / 256, 256>>>(b1);

    gemm2_kernel<<<(NN + 63) / 64, dim3(40, 8)>>>(W2);
    att2_kernel<<<(NN * 32 + 255) / 256, 256>>>(as2, ad2);

    int write_both = (out_size >= 2 * NN * NC) ? 1 : 0;
    agg2_kernel<<<(NN * 32 + 255) / 256, 256>>>(b2, out, write_both);
}

// round 4
// speedup vs baseline: 1.4534x; 1.0531x over previous
#include <cuda_runtime.h>
#include <cuda_bf16.h>
#include <cuda_fp16.h>
#include <math.h>

#define NN   50000
#define EE   800000
#define ETOT (EE + NN)
#define FIN  256
#define HC   128      // HEADS*C1 = 8*16
#define NC   40
#define NSLOPE 0.2f
#define NB_SCAN ((NN + 1023) / 1024)   // 49

// ---------------- scratch -----------------------------------------------
__device__ int      g_deg[NN];
__device__ int      g_off[NN + 1];
__device__ int      g_cur[NN];
__device__ int      g_src[ETOT];
__device__ int      g_dst[ETOT];
__device__ int      g_csr[ETOT];
__device__ unsigned g_state[NB_SCAN];       // lookback: (sum<<2)|flag
__device__ uint4    g_h1h[NN * HC / 8];     // h1 in fp16 (gather buffer)
__device__ float    g_as1[NN * 8];
__device__ float    g_ad1[NN * 8];
__device__ float    g_out1[NN * HC];
__device__ float    g_h2 [NN * NC];
__device__ float    g_as2[NN];
__device__ float    g_ad2[NN];

// packed fp32x2 FMA (sm_100+)
union F2 { unsigned long long u; float2 f; };
__device__ __forceinline__ void fma2(unsigned long long& d,
                                     unsigned long long a,
                                     unsigned long long b) {
    asm("fma.rn.f32x2 %0, %1, %2, %0;" : "+l"(d) : "l"(a), "l"(b));
}

// half2 <-> uint bit-cast
union H2U { unsigned u; __half2 h; };
__device__ __forceinline__ unsigned h2_to_u(__half2 h) { H2U c; c.h = h; return c.u; }
__device__ __forceinline__ float2 u_to_f2(unsigned u)  { H2U c; c.u = u; return __half22float2(c.h); }

// ---------------- preprocessing -----------------------------------------
__global__ void build_hist_kernel(const void* ei) {
    __shared__ int s_is64;
    if (threadIdx.x == 0) {
        const unsigned int* u = (const unsigned int*)ei;
        int is64 = 1;
        for (int k = 0; k < 8; k++)
            if (u[2 * k + 1] != 0u) is64 = 0;
        s_is64 = is64;
    }
    if (blockIdx.x == 0 && threadIdx.x < NB_SCAN)
        g_state[threadIdx.x] = 0u;
    __syncthreads();

    int e = blockIdx.x * blockDim.x + threadIdx.x;
    if (e >= ETOT) return;
    int s, d;
    if (e < EE) {
        if (s_is64) {
            const long long* p = (const long long*)ei;
            s = (int)p[e]; d = (int)p[EE + e];
        } else {
            const int* p = (const int*)ei;
            s = p[e]; d = p[EE + e];
        }
    } else {
        s = d = e - EE;
    }
    g_src[e] = s;
    g_dst[e] = d;
    atomicAdd(&g_deg[d], 1);
}

// single-kernel decoupled-lookback exclusive scan of g_deg -> g_off/g_cur
__global__ __launch_bounds__(1024) void scan_kernel() {
    __shared__ int wsum[32];
    __shared__ int s_excl;
    int tid = threadIdx.x, b = blockIdx.x;
    int lane = tid & 31, wid = tid >> 5;
    int i = b * 1024 + tid;
    int v = (i < NN) ? g_deg[i] : 0;

    int x = v;
#pragma unroll
    for (int o = 1; o < 32; o <<= 1) {
        int t = __shfl_up_sync(0xffffffffu, x, o);
        if (lane >= o) x += t;
    }
    if (lane == 31) wsum[wid] = x;
    __syncthreads();
    if (wid == 0) {
        int y = wsum[lane];
#pragma unroll
        for (int o = 1; o < 32; o <<= 1) {
            int t = __shfl_up_sync(0xffffffffu, y, o);
            if (lane >= o) y += t;
        }
        wsum[lane] = y;
    }
    __syncthreads();
    int incl = x + (wid > 0 ? wsum[wid - 1] : 0);
    int agg  = wsum[31];

    if (tid == 0) {
        unsigned ex = 0;
        if (b == 0) {
            atomicExch(&g_state[0], ((unsigned)agg << 2) | 2u);
        } else {
            atomicExch(&g_state[b], ((unsigned)agg << 2) | 1u);
            int j = b - 1;
            while (1) {
                unsigned st;
                do { st = atomicAdd(&g_state[j], 0u); } while ((st & 3u) == 0u);
                ex += st >> 2;
                if ((st & 3u) == 2u) break;
                j--;
            }
            atomicExch(&g_state[b], ((ex + (unsigned)agg) << 2) | 2u);
        }
        s_excl = (int)ex;
    }
    __syncthreads();
    if (i < NN) {
        int e = s_excl + incl - v;
        g_off[i] = e;
        g_cur[i] = e;
    }
    if (i == 0) g_off[NN] = ETOT;
}

__global__ void scatter_kernel() {
    int e = blockIdx.x * blockDim.x + threadIdx.x;
    if (e >= ETOT) return;
    int slot = atomicAdd(&g_cur[g_dst[e]], 1);
    g_csr[slot] = g_src[e];
}

// ---------------- GEMM1 + fused att1, fp16 h1 output ---------------------
// h1 = x[NN,256] @ W1[256,128]; BM=128, BN=128, BK=16, 256 thr, 8x8/thread
__global__ __launch_bounds__(256) void gemm1_kernel(const float* __restrict__ A,
                                                    const float* __restrict__ B,
                                                    const float* __restrict__ asv,
                                                    const float* __restrict__ adv) {
    __shared__ float As[2][16][132];
    __shared__ float Bs[2][16][128];
    int t = threadIdx.x;
    int row0 = blockIdx.x * 128;
    int tx = t & 15, ty = t >> 4;

    int am = t >> 1;
    int ak = (t & 1) * 8;
    int bk = t >> 4;
    int bn = (t & 15) * 8;

    F2 acc[8][4];
#pragma unroll
    for (int i = 0; i < 8; i++)
#pragma unroll
        for (int j = 0; j < 4; j++) acc[i][j].u = 0ull;

    float4 a0, a1, b0, b1;
    {
        int gr = row0 + am;
        if (gr < NN) {
            a0 = *(const float4*)&A[gr * FIN + ak];
            a1 = *(const float4*)&A[gr * FIN + ak + 4];
        } else { a0 = a1 = make_float4(0.f, 0.f, 0.f, 0.f); }
        b0 = *(const float4*)&B[bk * HC + bn];
        b1 = *(const float4*)&B[bk * HC + bn + 4];
    }
    As[0][ak + 0][am] = a0.x; As[0][ak + 1][am] = a0.y;
    As[0][ak + 2][am] = a0.z; As[0][ak + 3][am] = a0.w;
    As[0][ak + 4][am] = a1.x; As[0][ak + 5][am] = a1.y;
    As[0][ak + 6][am] = a1.z; As[0][ak + 7][am] = a1.w;
    *(float4*)&Bs[0][bk][bn]     = b0;
    *(float4*)&Bs[0][bk][bn + 4] = b1;
    __syncthreads();

    for (int it = 0; it < 16; it++) {
        int cur = it & 1;
        if (it < 15) {
            int k0 = (it + 1) * 16;
            int gr = row0 + am;
            if (gr < NN) {
                a0 = *(const float4*)&A[gr * FIN + k0 + ak];
                a1 = *(const float4*)&A[gr * FIN + k0 + ak + 4];
            } else { a0 = a1 = make_float4(0.f, 0.f, 0.f, 0.f); }
            b0 = *(const float4*)&B[(k0 + bk) * HC + bn];
            b1 = *(const float4*)&B[(k0 + bk) * HC + bn + 4];
        }
#pragma unroll
        for (int k = 0; k < 16; k++) {
            float4 ra0 = *(const float4*)&As[cur][k][ty * 8];
            float4 ra1 = *(const float4*)&As[cur][k][ty * 8 + 4];
            const float2* pb = (const float2*)&Bs[cur][k][tx * 8];
            F2 bb[4];
#pragma unroll
            for (int j = 0; j < 4; j++) bb[j].f = pb[j];
            float av[8] = {ra0.x, ra0.y, ra0.z, ra0.w, ra1.x, ra1.y, ra1.z, ra1.w};
#pragma unroll
            for (int i = 0; i < 8; i++) {
                F2 ad; ad.f.x = av[i]; ad.f.y = av[i];
#pragma unroll
                for (int j = 0; j < 4; j++) fma2(acc[i][j].u, ad.u, bb[j].u);
            }
        }
        if (it < 15) {
            int nb = cur ^ 1;
            As[nb][ak + 0][am] = a0.x; As[nb][ak + 1][am] = a0.y;
            As[nb][ak + 2][am] = a0.z; As[nb][ak + 3][am] = a0.w;
            As[nb][ak + 4][am] = a1.x; As[nb][ak + 5][am] = a1.y;
            As[nb][ak + 6][am] = a1.z; As[nb][ak + 7][am] = a1.w;
            *(float4*)&Bs[nb][bk][bn]     = b0;
            *(float4*)&Bs[nb][bk][bn + 4] = b1;
            __syncthreads();
        }
    }

    // epilogue: fp16 h1 store + fused attention logits (fp32 accumulators)
    int head = tx >> 1;
    int abase = head * 16 + (tx & 1) * 8;
    float asr[8], adr[8];
#pragma unroll
    for (int j = 0; j < 8; j++) { asr[j] = asv[abase + j]; adr[j] = adv[abase + j]; }

    __half* h1h = (__half*)g_h1h;
#pragma unroll
    for (int i = 0; i < 8; i++) {
        int gr = row0 + ty * 8 + i;
        float h[8];
#pragma unroll
        for (int j = 0; j < 4; j++) { h[2 * j] = acc[i][j].f.x; h[2 * j + 1] = acc[i][j].f.y; }
        if (gr < NN) {
            uint4 pk;
            pk.x = h2_to_u(__floats2half2_rn(h[0], h[1]));
            pk.y = h2_to_u(__floats2half2_rn(h[2], h[3]));
            pk.z = h2_to_u(__floats2half2_rn(h[4], h[5]));
            pk.w = h2_to_u(__floats2half2_rn(h[6], h[7]));
            *(uint4*)&h1h[gr * HC + tx * 8] = pk;
        }
        float s = 0.f, d = 0.f;
#pragma unroll
        for (int j = 0; j < 8; j++) { s += h[j] * asr[j]; d += h[j] * adr[j]; }
        s += __shfl_xor_sync(0xffffffffu, s, 1);
        d += __shfl_xor_sync(0xffffffffu, d, 1);
        if (((t & 1) == 0) && gr < NN) {
            g_as1[gr * 8 + head] = s;
            g_ad1[gr * 8 + head] = d;
        }
    }
}

// ---------------- layer 1 aggregation (fp16 gather) ----------------------
__global__ __launch_bounds__(256) void agg1_kernel(const float* __restrict__ b1) {
    int gw = (blockIdx.x * blockDim.x + threadIdx.x) >> 5;
    int lane = threadIdx.x & 31;
    if (gw >= NN) return;
    int n = gw;
    int beg = g_off[n], end = g_off[n + 1];

    int h8 = lane & 7;
    int eg = lane >> 3;
    float adst = g_ad1[n * 8 + h8];

    float mymax = -1e30f;
    for (int i = beg + eg; i < end; i += 4) {
        int s = g_csr[i];
        float ev = g_as1[s * 8 + h8] + adst;
        ev = ev > 0.f ? ev : NSLOPE * ev;
        mymax = fmaxf(mymax, ev);
    }
    mymax = fmaxf(mymax, __shfl_xor_sync(0xffffffffu, mymax, 8));
    mymax = fmaxf(mymax, __shfl_xor_sync(0xffffffffu, mymax, 16));
    float m = mymax;

    float acc0 = 0.f, acc1 = 0.f, acc2 = 0.f, acc3 = 0.f;
    float denom = 0.f;
    int head = lane >> 2;
    const uint2* h1v = (const uint2*)g_h1h;   // 32 uint2 per node row

    int i = beg;
    for (; i + 2 <= end; i += 2) {
        int s0 = g_csr[i], s1 = g_csr[i + 1];
        uint2 r0 = h1v[s0 * 32 + lane];
        uint2 r1 = h1v[s1 * 32 + lane];
        float p0 = 0.f, p1 = 0.f;
        if (lane < 8) {
            float e0 = g_as1[s0 * 8 + lane] + adst;
            e0 = e0 > 0.f ? e0 : NSLOPE * e0;
            p0 = __expf(e0 - m);
            float e1 = g_as1[s1 * 8 + lane] + adst;
            e1 = e1 > 0.f ? e1 : NSLOPE * e1;
            p1 = __expf(e1 - m);
            denom += p0 + p1;
        }
        float ph0 = __shfl_sync(0xffffffffu, p0, head);
        float ph1 = __shfl_sync(0xffffffffu, p1, head);
        float2 f00 = u_to_f2(r0.x);
        float2 f01 = u_to_f2(r0.y);
        float2 f10 = u_to_f2(r1.x);
        float2 f11 = u_to_f2(r1.y);
        acc0 += ph0 * f00.x + ph1 * f10.x;
        acc1 += ph0 * f00.y + ph1 * f10.y;
        acc2 += ph0 * f01.x + ph1 * f11.x;
        acc3 += ph0 * f01.y + ph1 * f11.y;
    }
    for (; i < end; i++) {
        int s = g_csr[i];
        uint2 r0 = h1v[s * 32 + lane];
        float p = 0.f;
        if (lane < 8) {
            float ev = g_as1[s * 8 + lane] + adst;
            ev = ev > 0.f ? ev : NSLOPE * ev;
            p = __expf(ev - m);
            denom += p;
        }
        float ph = __shfl_sync(0xffffffffu, p, head);
        float2 f0 = u_to_f2(r0.x);
        float2 f1 = u_to_f2(r0.y);
        acc0 += ph * f0.x; acc1 += ph * f0.y;
        acc2 += ph * f1.x; acc3 += ph * f1.y;
    }
    float dh = __shfl_sync(0xffffffffu, denom, head);
    float inv = 1.f / (dh + 1e-16f);
    int ch = lane * 4;
    float v[4] = {acc0 * inv + b1[ch], acc1 * inv + b1[ch + 1],
                  acc2 * inv + b1[ch + 2], acc3 * inv + b1[ch + 3]};
#pragma unroll
    for (int j = 0; j < 4; j++)
        v[j] = v[j] > 0.f ? v[j] : expm1f(v[j]);
    ((float4*)g_out1)[n * 32 + lane] = make_float4(v[0], v[1], v[2], v[3]);
}

// ---------------- GEMM2 + fused att2 -------------------------------------
__global__ __launch_bounds__(320) void gemm2_kernel(const float* __restrict__ W,
                                                    const float* __restrict__ asv,
                                                    const float* __restrict__ adv) {
    __shared__ float s_w[HC * NC];       // 20 KB
    __shared__ float s_x[64 * HC];       // 32 KB (reused as s_h2 after loop)
    int c = threadIdx.x;   // 0..39
    int r = threadIdx.y;   // 0..7
    int t = threadIdx.y * 40 + threadIdx.x;
    int row0 = blockIdx.x * 64;

    for (int i = t; i < HC * NC; i += 320) s_w[i] = W[i];
    for (int i = t; i < 64 * (HC / 4); i += 320) {
        int rr = i >> 5, kq = (i & 31) * 4;
        int gr = row0 + rr;
        float4 v = make_float4(0.f, 0.f, 0.f, 0.f);
        if (gr < NN) v = *(const float4*)&g_out1[gr * HC + kq];
        *(float4*)&s_x[rr * HC + kq] = v;
    }
    __syncthreads();

    float acc[8] = {0.f, 0.f, 0.f, 0.f, 0.f, 0.f, 0.f, 0.f};
    for (int k4 = 0; k4 < HC; k4 += 4) {
        float w0 = s_w[(k4 + 0) * NC + c];
        float w1 = s_w[(k4 + 1) * NC + c];
        float w2 = s_w[(k4 + 2) * NC + c];
        float w3 = s_w[(k4 + 3) * NC + c];
#pragma unroll
        for (int i = 0; i < 8; i++) {
            float4 xv = *(const float4*)&s_x[(r + 8 * i) * HC + k4];
            acc[i] += w0 * xv.x + w1 * xv.y + w2 * xv.z + w3 * xv.w;
        }
    }
#pragma unroll
    for (int i = 0; i < 8; i++) {
        int gr = row0 + r + 8 * i;
        if (gr < NN) g_h2[gr * NC + c] = acc[i];
    }

    // fused att2: reuse s_x as [64][40] h2 tile
    __syncthreads();
    float* s_h2 = s_x;
#pragma unroll
    for (int i = 0; i < 8; i++)
        s_h2[(r + 8 * i) * NC + c] = acc[i];
    __syncthreads();
    if (t < 64) {
        int gr = row0 + t;
        if (gr < NN) {
            float s = 0.f, d = 0.f;
#pragma unroll
            for (int cc = 0; cc < NC; cc++) {
                float hv = s_h2[t * NC + cc];
                s += hv * asv[cc];
                d += hv * adv[cc];
            }
            g_as2[gr] = s;
            g_ad2[gr] = d;
        }
    }
}

// ---------------- layer 2 aggregation + log_softmax ----------------------
__global__ __launch_bounds__(256) void agg2_kernel(const float* __restrict__ b2,
                                                   float* __restrict__ out,
                                                   int write_both) {
    int gw = (blockIdx.x * blockDim.x + threadIdx.x) >> 5;
    int lane = threadIdx.x & 31;
    if (gw >= NN) return;
    int n = gw;
    int beg = g_off[n], end = g_off[n + 1];
    float adst = g_ad2[n];

    float mymax = -1e30f;
    for (int i = beg + lane; i < end; i += 32) {
        int s = g_csr[i];
        float ev = g_as2[s] + adst;
        ev = ev > 0.f ? ev : NSLOPE * ev;
        mymax = fmaxf(mymax, ev);
    }
#pragma unroll
    for (int o = 16; o > 0; o >>= 1)
        mymax = fmaxf(mymax, __shfl_xor_sync(0xffffffffu, mymax, o));
    float m = mymax;

    float acc0 = 0.f, acc1 = 0.f, denom = 0.f;
    int i = beg;
    for (; i + 2 <= end; i += 2) {
        int s0 = g_csr[i], s1 = g_csr[i + 1];
        float x00 = g_h2[s0 * NC + lane];
        float x10 = g_h2[s1 * NC + lane];
        float x01 = (lane < 8) ? g_h2[s0 * NC + 32 + lane] : 0.f;
        float x11 = (lane < 8) ? g_h2[s1 * NC + 32 + lane] : 0.f;
        float e0 = g_as2[s0] + adst; e0 = e0 > 0.f ? e0 : NSLOPE * e0;
        float e1 = g_as2[s1] + adst; e1 = e1 > 0.f ? e1 : NSLOPE * e1;
        float p0 = __expf(e0 - m), p1 = __expf(e1 - m);
        denom += p0 + p1;
        acc0 += p0 * x00 + p1 * x10;
        acc1 += p0 * x01 + p1 * x11;
    }
    for (; i < end; i++) {
        int s = g_csr[i];
        float x0 = g_h2[s * NC + lane];
        float x1 = (lane < 8) ? g_h2[s * NC + 32 + lane] : 0.f;
        float ev = g_as2[s] + adst;
        ev = ev > 0.f ? ev : NSLOPE * ev;
        float p = __expf(ev - m);
        denom += p;
        acc0 += p * x0;
        acc1 += p * x1;
    }
    float inv = 1.f / (denom + 1e-16f);
    float v0 = acc0 * inv + b2[lane];
    float v1 = (lane < 8) ? acc1 * inv + b2[32 + lane] : -1e30f;

    float rmax = fmaxf(v0, v1);
#pragma unroll
    for (int o = 16; o > 0; o >>= 1)
        rmax = fmaxf(rmax, __shfl_xor_sync(0xffffffffu, rmax, o));
    float se = expf(v0 - rmax) + ((lane < 8) ? expf(v1 - rmax) : 0.f);
#pragma unroll
    for (int o = 16; o > 0; o >>= 1)
        se += __shfl_xor_sync(0xffffffffu, se, o);
    float lse = rmax + logf(se);

    out[n * NC + lane] = v0;
    if (lane < 8) out[n * NC + 32 + lane] = v1;
    if (write_both) {
        float* o2 = out + (size_t)NN * NC;
        o2[n * NC + lane] = v0 - lse;
        if (lane < 8) o2[n * NC + 32 + lane] = v1 - lse;
    }
}

// ---------------- launch --------------------------------------------------
extern "C" void kernel_launch(void* const* d_in, const int* in_sizes, int n_in,
                              void* d_out, int out_size) {
    const float* x   = (const float*)d_in[0];
    const void*  ei  = d_in[1];
    const float* W1  = (const float*)d_in[3];
    const float* as1 = (const float*)d_in[4];
    const float* ad1 = (const float*)d_in[5];
    const float* b1  = (const float*)d_in[6];
    const float* W2  = (const float*)d_in[7];
    const float* as2 = (const float*)d_in[8];
    const float* ad2 = (const float*)d_in[9];
    const float* b2  = (const float*)d_in[10];
    float* out = (float*)d_out;
    (void)in_sizes; (void)n_in;

    void* deg_ptr = nullptr;
    cudaGetSymbolAddress(&deg_ptr, g_deg);
    cudaMemsetAsync(deg_ptr, 0, NN * sizeof(int));

    build_hist_kernel<<<(ETOT + 255) / 256, 256>>>(ei);
    scan_kernel<<<NB_SCAN, 1024>>>();
    scatter_kernel<<<(ETOT + 255) / 256, 256>>>();

    gemm1_kernel<<<(NN + 127) / 128, 256>>>(x, W1, as1, ad1);
    agg1_kernel<<<(NN * 32 + 255) / 256, 256>>>(b1);

    gemm2_kernel<<<(NN + 63) / 64, dim3(40, 8)>>>(W2, as2, ad2);

    int write_both = (out_size >= 2 * NN * NC) ? 1 : 0;
    agg2_kernel<<<(NN * 32 + 255) / 256, 256>>>(b2, out, write_both);
}